// round 15
// baseline (speedup 1.0000x reference)
#include <cuda_runtime.h>

// MaskedNorm: X[B,N,D] fp32, mask[B,N] int32 (1 == masked out), W[D], b[D].
// out = mask ? b : (X - mean_n)/std_n * W + b   (std unbiased, ddof=1; REPLACE=0)
#define Bz 64
#define Nz 8192
#define Dz 128
#define D4 32          // D/4 float4 lanes
#define SPLITS 16      // stats blocks per batch
#define ROWS_PER_SPLIT (Nz / SPLITS)   // 512
#define RPB 256        // rows per block in normalize kernel
#define GROUPS 4
#define GB (Bz / GROUPS)               // 16 batches per group (~32MB valid X)

// Per-split partials: every slot is overwritten on every launch.
// -> no zero kernel, no atomics, deterministic under graph replay.
__device__ float g_psum[SPLITS][Bz * Dz];
__device__ float g_psq [SPLITS][Bz * Dz];
__device__ int   g_pcnt[SPLITS][Bz];

// grid (SPLITS, GB), block 256.  Warp rg handles rows rg, rg+8, ... (64 rows).
// Unroll 4 with mask prefetch: 4 independent mask LDGs issue first, then up to
// 4 conditional float4 loads batch together -> MLP_p1 ~4.
__global__ void mn_stats_kernel(const float* __restrict__ X,
                                const int* __restrict__ mask, int b0) {
    const int b     = b0 + blockIdx.y;
    const int split = blockIdx.x;
    const int tid   = threadIdx.x;
    const int d4    = tid & 31;    // float4 lane in D
    const int rg    = tid >> 5;    // row group 0..7 (== warp id)
    const int row0  = split * ROWS_PER_SPLIT;

    const float4* Xb = (const float4*)(X + (size_t)b * Nz * Dz);
    const int*    mb = mask + (size_t)b * Nz;

    float4 s = make_float4(0.f, 0.f, 0.f, 0.f);
    float4 q = make_float4(0.f, 0.f, 0.f, 0.f);
    int cnt = 0;

    for (int r = row0 + rg; r < row0 + ROWS_PER_SPLIT; r += 32) {
        const int m0 = mb[r];
        const int m1 = mb[r + 8];
        const int m2 = mb[r + 16];
        const int m3 = mb[r + 24];
        if (!m0) {
            float4 v = Xb[(size_t)r * D4 + d4];
            s.x += v.x; s.y += v.y; s.z += v.z; s.w += v.w;
            q.x = fmaf(v.x, v.x, q.x); q.y = fmaf(v.y, v.y, q.y);
            q.z = fmaf(v.z, v.z, q.z); q.w = fmaf(v.w, v.w, q.w);
            cnt++;
        }
        if (!m1) {
            float4 v = Xb[(size_t)(r + 8) * D4 + d4];
            s.x += v.x; s.y += v.y; s.z += v.z; s.w += v.w;
            q.x = fmaf(v.x, v.x, q.x); q.y = fmaf(v.y, v.y, q.y);
            q.z = fmaf(v.z, v.z, q.z); q.w = fmaf(v.w, v.w, q.w);
            cnt++;
        }
        if (!m2) {
            float4 v = Xb[(size_t)(r + 16) * D4 + d4];
            s.x += v.x; s.y += v.y; s.z += v.z; s.w += v.w;
            q.x = fmaf(v.x, v.x, q.x); q.y = fmaf(v.y, v.y, q.y);
            q.z = fmaf(v.z, v.z, q.z); q.w = fmaf(v.w, v.w, q.w);
            cnt++;
        }
        if (!m3) {
            float4 v = Xb[(size_t)(r + 24) * D4 + d4];
            s.x += v.x; s.y += v.y; s.z += v.z; s.w += v.w;
            q.x = fmaf(v.x, v.x, q.x); q.y = fmaf(v.y, v.y, q.y);
            q.z = fmaf(v.z, v.z, q.z); q.w = fmaf(v.w, v.w, q.w);
            cnt++;
        }
    }

    __shared__ float ssum[8][Dz];
    __shared__ float ssq[8][Dz];
    __shared__ int   scnt[8];
    ((float4*)&ssum[rg][0])[d4] = s;
    ((float4*)&ssq[rg][0])[d4]  = q;
    if (d4 == 0) scnt[rg] = cnt;
    __syncthreads();

    if (tid < Dz) {
        float ts = 0.f, tq = 0.f;
        #pragma unroll
        for (int i = 0; i < 8; i++) { ts += ssum[i][tid]; tq += ssq[i][tid]; }
        g_psum[split][b * Dz + tid] = ts;      // plain store, overwritten every launch
        g_psq [split][b * Dz + tid] = tq;
    }
    if (tid == 0) {
        int c = 0;
        #pragma unroll
        for (int i = 0; i < 8; i++) c += scnt[i];
        g_pcnt[split][b] = c;
    }
}

// grid (N/RPB, GB), block 256.
// LIFO within the group (b = b0 + GB-1 - blockIdx.y).  Loads .cs (read-once),
// stores .cs (evict-first).  Unroll 4 (proven MLP point).  Masks staged in smem.
__global__ void mn_norm_kernel(const float* __restrict__ X,
                               const int* __restrict__ mask,
                               const float* __restrict__ W,
                               const float* __restrict__ bias,
                               float* __restrict__ out, int b0) {
    const int b   = b0 + (GB - 1 - blockIdx.y);   // LIFO within group
    const int tid = threadIdx.x;

    __shared__ float sa[Dz];   // W * invstd
    __shared__ float sc[Dz];   // bias - mean * W * invstd
    __shared__ float sr[Dz];   // replacement value: 0*W + bias
    __shared__ int   smask[RPB];

    const int row0 = blockIdx.x * RPB;
    const int*  mb = mask + (size_t)b * Nz;

    smask[tid] = mb[row0 + tid];           // one coalesced 1KB burst

    if (tid < Dz) {
        float ts = 0.f, tq = 0.f;
        int   c  = 0;
        #pragma unroll
        for (int s = 0; s < SPLITS; s++) {
            ts += g_psum[s][b * Dz + tid];
            tq += g_psq [s][b * Dz + tid];
            c  += g_pcnt[s][b];
        }
        float fc   = (float)c;
        float mean = ts / fc;
        float var  = (tq - fc * mean * mean) / (fc - 1.0f);
        float inv  = rsqrtf(var);
        float w    = W[tid];
        float bb   = bias[tid];
        float a    = w * inv;
        sa[tid] = a;
        sc[tid] = bb - mean * a;
        sr[tid] = bb;
    }
    __syncthreads();

    const int d4 = tid & 31;
    const int rg = tid >> 5;
    const int dd = d4 * 4;

    const float4* Xb = (const float4*)(X + (size_t)b * Nz * Dz);
    float4*       Ob = (float4*)(out + (size_t)b * Nz * Dz);

    const float a0 = sa[dd], a1 = sa[dd + 1], a2 = sa[dd + 2], a3 = sa[dd + 3];
    const float c0 = sc[dd], c1 = sc[dd + 1], c2 = sc[dd + 2], c3 = sc[dd + 3];
    float4 rv;
    rv.x = sr[dd]; rv.y = sr[dd + 1]; rv.z = sr[dd + 2]; rv.w = sr[dd + 3];

    // 32 rows per warp, unroll 4.  All loads unconditional (masked rows
    // redirected to L2-hot batch row 0 -> no DRAM cost); FSEL output select.
    for (int rr = rg; rr < RPB; rr += 32) {
        const int rA = row0 + rr;
        const int rB = rA + 8, rC = rA + 16, rD = rA + 24;
        const int m0 = smask[rr];
        const int m1 = smask[rr + 8];
        const int m2 = smask[rr + 16];
        const int m3 = smask[rr + 24];

        const size_t i0 = m0 ? (size_t)d4 : (size_t)rA * D4 + d4;
        const size_t i1 = m1 ? (size_t)d4 : (size_t)rB * D4 + d4;
        const size_t i2 = m2 ? (size_t)d4 : (size_t)rC * D4 + d4;
        const size_t i3 = m3 ? (size_t)d4 : (size_t)rD * D4 + d4;

        const float4 v0 = __ldcs(&Xb[i0]);
        const float4 v1 = __ldcs(&Xb[i1]);
        const float4 v2 = __ldcs(&Xb[i2]);
        const float4 v3 = __ldcs(&Xb[i3]);

        float4 o0, o1, o2, o3;
        o0.x = m0 ? rv.x : fmaf(v0.x, a0, c0);
        o0.y = m0 ? rv.y : fmaf(v0.y, a1, c1);
        o0.z = m0 ? rv.z : fmaf(v0.z, a2, c2);
        o0.w = m0 ? rv.w : fmaf(v0.w, a3, c3);

        o1.x = m1 ? rv.x : fmaf(v1.x, a0, c0);
        o1.y = m1 ? rv.y : fmaf(v1.y, a1, c1);
        o1.z = m1 ? rv.z : fmaf(v1.z, a2, c2);
        o1.w = m1 ? rv.w : fmaf(v1.w, a3, c3);

        o2.x = m2 ? rv.x : fmaf(v2.x, a0, c0);
        o2.y = m2 ? rv.y : fmaf(v2.y, a1, c1);
        o2.z = m2 ? rv.z : fmaf(v2.z, a2, c2);
        o2.w = m2 ? rv.w : fmaf(v2.w, a3, c3);

        o3.x = m3 ? rv.x : fmaf(v3.x, a0, c0);
        o3.y = m3 ? rv.y : fmaf(v3.y, a1, c1);
        o3.z = m3 ? rv.z : fmaf(v3.z, a2, c2);
        o3.w = m3 ? rv.w : fmaf(v3.w, a3, c3);

        __stcs(&Ob[(size_t)rA * D4 + d4], o0);
        __stcs(&Ob[(size_t)rB * D4 + d4], o1);
        __stcs(&Ob[(size_t)rC * D4 + d4], o2);
        __stcs(&Ob[(size_t)rD * D4 + d4], o3);
    }
}

extern "C" void kernel_launch(void* const* d_in, const int* in_sizes, int n_in,
                              void* d_out, int out_size) {
    const float* X    = (const float*)d_in[0];
    const int*   mask = (const int*)d_in[1];
    const float* W    = (const float*)d_in[2];
    const float* bias = (const float*)d_in[3];
    float* out        = (float*)d_out;

    dim3 gs(SPLITS, GB);
    dim3 gn(Nz / RPB, GB);

    // Software pipeline over 4 batch-groups in ONE stream:
    //   s0, s1, n0, s2, n1, s3, n2, n3
    // Only one group's stats reads (~32MB) intervene between stats(g) and
    // norm(g), so norm(g)'s X reads hit the L2-resident set.
    mn_stats_kernel<<<gs, 256>>>(X, mask, 0 * GB);
    mn_stats_kernel<<<gs, 256>>>(X, mask, 1 * GB);
    mn_norm_kernel<<<gn, 256>>>(X, mask, W, bias, out, 0 * GB);
    mn_stats_kernel<<<gs, 256>>>(X, mask, 2 * GB);
    mn_norm_kernel<<<gn, 256>>>(X, mask, W, bias, out, 1 * GB);
    mn_stats_kernel<<<gs, 256>>>(X, mask, 3 * GB);
    mn_norm_kernel<<<gn, 256>>>(X, mask, W, bias, out, 2 * GB);
    mn_norm_kernel<<<gn, 256>>>(X, mask, W, bias, out, 3 * GB);
}

// round 16
// speedup vs baseline: 1.6148x; 1.6148x over previous
#include <cuda_runtime.h>

// MaskedNorm: X[B,N,D] fp32, mask[B,N] int32 (1 == masked out), W[D], b[D].
// out = mask ? b : (X - mean_n)/std_n * W + b   (std unbiased, ddof=1; REPLACE=0)
#define Bz 64
#define Nz 8192
#define Dz 128
#define D4 32          // D/4 float4 lanes
#define SPLITS 16      // stats blocks per batch
#define ROWS_PER_SPLIT (Nz / SPLITS)   // 512
#define RPB 256        // rows per block in normalize kernel

// Per-split partials: every slot is overwritten on every launch.
// -> no zero kernel, no atomics, deterministic under graph replay.
__device__ float g_psum[SPLITS][Bz * Dz];
__device__ float g_psq [SPLITS][Bz * Dz];
__device__ int   g_pcnt[SPLITS][Bz];

// grid (SPLITS, B), block 256.  Warp rg handles rows rg, rg+8, ... (64 rows).
// Unroll 4 with mask prefetch: 4 independent mask LDGs issue first, then up to
// 4 conditional float4 loads batch together -> MLP_p1 ~4.
__global__ void mn_stats_kernel(const float* __restrict__ X,
                                const int* __restrict__ mask) {
    const int b     = blockIdx.y;
    const int split = blockIdx.x;
    const int tid   = threadIdx.x;
    const int d4    = tid & 31;    // float4 lane in D
    const int rg    = tid >> 5;    // row group 0..7 (== warp id)
    const int row0  = split * ROWS_PER_SPLIT;

    const float4* Xb = (const float4*)(X + (size_t)b * Nz * Dz);
    const int*    mb = mask + (size_t)b * Nz;

    float4 s = make_float4(0.f, 0.f, 0.f, 0.f);
    float4 q = make_float4(0.f, 0.f, 0.f, 0.f);
    int cnt = 0;

    for (int r = row0 + rg; r < row0 + ROWS_PER_SPLIT; r += 32) {
        const int m0 = mb[r];
        const int m1 = mb[r + 8];
        const int m2 = mb[r + 16];
        const int m3 = mb[r + 24];
        if (!m0) {
            float4 v = Xb[(size_t)r * D4 + d4];
            s.x += v.x; s.y += v.y; s.z += v.z; s.w += v.w;
            q.x = fmaf(v.x, v.x, q.x); q.y = fmaf(v.y, v.y, q.y);
            q.z = fmaf(v.z, v.z, q.z); q.w = fmaf(v.w, v.w, q.w);
            cnt++;
        }
        if (!m1) {
            float4 v = Xb[(size_t)(r + 8) * D4 + d4];
            s.x += v.x; s.y += v.y; s.z += v.z; s.w += v.w;
            q.x = fmaf(v.x, v.x, q.x); q.y = fmaf(v.y, v.y, q.y);
            q.z = fmaf(v.z, v.z, q.z); q.w = fmaf(v.w, v.w, q.w);
            cnt++;
        }
        if (!m2) {
            float4 v = Xb[(size_t)(r + 16) * D4 + d4];
            s.x += v.x; s.y += v.y; s.z += v.z; s.w += v.w;
            q.x = fmaf(v.x, v.x, q.x); q.y = fmaf(v.y, v.y, q.y);
            q.z = fmaf(v.z, v.z, q.z); q.w = fmaf(v.w, v.w, q.w);
            cnt++;
        }
        if (!m3) {
            float4 v = Xb[(size_t)(r + 24) * D4 + d4];
            s.x += v.x; s.y += v.y; s.z += v.z; s.w += v.w;
            q.x = fmaf(v.x, v.x, q.x); q.y = fmaf(v.y, v.y, q.y);
            q.z = fmaf(v.z, v.z, q.z); q.w = fmaf(v.w, v.w, q.w);
            cnt++;
        }
    }

    __shared__ float ssum[8][Dz];
    __shared__ float ssq[8][Dz];
    __shared__ int   scnt[8];
    ((float4*)&ssum[rg][0])[d4] = s;
    ((float4*)&ssq[rg][0])[d4]  = q;
    if (d4 == 0) scnt[rg] = cnt;
    __syncthreads();

    if (tid < Dz) {
        float ts = 0.f, tq = 0.f;
        #pragma unroll
        for (int i = 0; i < 8; i++) { ts += ssum[i][tid]; tq += ssq[i][tid]; }
        g_psum[split][b * Dz + tid] = ts;      // plain store, overwritten every launch
        g_psq [split][b * Dz + tid] = tq;
    }
    if (tid == 0) {
        int c = 0;
        #pragma unroll
        for (int i = 0; i < 8; i++) c += scnt[i];
        g_pcnt[split][b] = c;
    }
}

// grid (N/RPB, B), block 256.  Launched with PDL (programmatic stream
// serialization): blocks dispatch while stats drains, run the stats-
// independent prologue (mask staging, W/bias loads), then grid-sync before
// reducing the partials.  LIFO batch traversal; .cs loads/stores; unroll 4.
__global__ void mn_norm_kernel(const float* __restrict__ X,
                               const int* __restrict__ mask,
                               const float* __restrict__ W,
                               const float* __restrict__ bias,
                               float* __restrict__ out) {
    const int b   = Bz - 1 - blockIdx.y;    // reverse: most-recently-warmed first
    const int tid = threadIdx.x;

    __shared__ float sa[Dz];   // W * invstd
    __shared__ float sc[Dz];   // bias - mean * W * invstd
    __shared__ float sr[Dz];   // replacement value: 0*W + bias
    __shared__ int   smask[RPB];

    const int row0 = blockIdx.x * RPB;
    const int*  mb = mask + (size_t)b * Nz;

    // ---- stats-independent prologue (overlaps stats tail under PDL) ----
    smask[tid] = mb[row0 + tid];           // one coalesced 1KB burst
    float w = 0.f, bb = 0.f;
    if (tid < Dz) { w = W[tid]; bb = bias[tid]; }

    // ---- wait for stats grid completion (memory visible) ----
    cudaGridDependencySynchronize();

    if (tid < Dz) {
        float ts = 0.f, tq = 0.f;
        int   c  = 0;
        #pragma unroll
        for (int s = 0; s < SPLITS; s++) {
            ts += g_psum[s][b * Dz + tid];
            tq += g_psq [s][b * Dz + tid];
            c  += g_pcnt[s][b];
        }
        float fc   = (float)c;
        float mean = ts / fc;
        float var  = (tq - fc * mean * mean) / (fc - 1.0f);
        float inv  = rsqrtf(var);
        float a    = w * inv;
        sa[tid] = a;
        sc[tid] = bb - mean * a;
        sr[tid] = bb;
    }
    __syncthreads();

    const int d4 = tid & 31;
    const int rg = tid >> 5;
    const int dd = d4 * 4;

    const float4* Xb = (const float4*)(X + (size_t)b * Nz * Dz);
    float4*       Ob = (float4*)(out + (size_t)b * Nz * Dz);

    const float a0 = sa[dd], a1 = sa[dd + 1], a2 = sa[dd + 2], a3 = sa[dd + 3];
    const float c0 = sc[dd], c1 = sc[dd + 1], c2 = sc[dd + 2], c3 = sc[dd + 3];
    float4 rv;
    rv.x = sr[dd]; rv.y = sr[dd + 1]; rv.z = sr[dd + 2]; rv.w = sr[dd + 3];

    // 32 rows per warp, unroll 4.  All loads unconditional (masked rows
    // redirected to L2-hot batch row 0 -> no DRAM cost); FSEL output select.
    for (int rr = rg; rr < RPB; rr += 32) {
        const int rA = row0 + rr;
        const int rB = rA + 8, rC = rA + 16, rD = rA + 24;
        const int m0 = smask[rr];
        const int m1 = smask[rr + 8];
        const int m2 = smask[rr + 16];
        const int m3 = smask[rr + 24];

        const size_t i0 = m0 ? (size_t)d4 : (size_t)rA * D4 + d4;
        const size_t i1 = m1 ? (size_t)d4 : (size_t)rB * D4 + d4;
        const size_t i2 = m2 ? (size_t)d4 : (size_t)rC * D4 + d4;
        const size_t i3 = m3 ? (size_t)d4 : (size_t)rD * D4 + d4;

        const float4 v0 = __ldcs(&Xb[i0]);
        const float4 v1 = __ldcs(&Xb[i1]);
        const float4 v2 = __ldcs(&Xb[i2]);
        const float4 v3 = __ldcs(&Xb[i3]);

        float4 o0, o1, o2, o3;
        o0.x = m0 ? rv.x : fmaf(v0.x, a0, c0);
        o0.y = m0 ? rv.y : fmaf(v0.y, a1, c1);
        o0.z = m0 ? rv.z : fmaf(v0.z, a2, c2);
        o0.w = m0 ? rv.w : fmaf(v0.w, a3, c3);

        o1.x = m1 ? rv.x : fmaf(v1.x, a0, c0);
        o1.y = m1 ? rv.y : fmaf(v1.y, a1, c1);
        o1.z = m1 ? rv.z : fmaf(v1.z, a2, c2);
        o1.w = m1 ? rv.w : fmaf(v1.w, a3, c3);

        o2.x = m2 ? rv.x : fmaf(v2.x, a0, c0);
        o2.y = m2 ? rv.y : fmaf(v2.y, a1, c1);
        o2.z = m2 ? rv.z : fmaf(v2.z, a2, c2);
        o2.w = m2 ? rv.w : fmaf(v2.w, a3, c3);

        o3.x = m3 ? rv.x : fmaf(v3.x, a0, c0);
        o3.y = m3 ? rv.y : fmaf(v3.y, a1, c1);
        o3.z = m3 ? rv.z : fmaf(v3.z, a2, c2);
        o3.w = m3 ? rv.w : fmaf(v3.w, a3, c3);

        __stcs(&Ob[(size_t)rA * D4 + d4], o0);
        __stcs(&Ob[(size_t)rB * D4 + d4], o1);
        __stcs(&Ob[(size_t)rC * D4 + d4], o2);
        __stcs(&Ob[(size_t)rD * D4 + d4], o3);
    }
}

extern "C" void kernel_launch(void* const* d_in, const int* in_sizes, int n_in,
                              void* d_out, int out_size) {
    const float* X    = (const float*)d_in[0];
    const int*   mask = (const int*)d_in[1];
    const float* W    = (const float*)d_in[2];
    const float* bias = (const float*)d_in[3];
    float* out        = (float*)d_out;

    dim3 g1(SPLITS, Bz);
    mn_stats_kernel<<<g1, 256>>>(X, mask);

    // PDL launch: norm blocks dispatch while stats drains; the in-kernel
    // cudaGridDependencySynchronize() enforces the data dependency.
    dim3 g2(Nz / RPB, Bz);
    cudaLaunchConfig_t cfg = {};
    cfg.gridDim  = g2;
    cfg.blockDim = dim3(256, 1, 1);
    cfg.stream   = 0;
    cudaLaunchAttribute attrs[1];
    attrs[0].id = cudaLaunchAttributeProgrammaticStreamSerialization;
    attrs[0].val.programmaticStreamSerializationAllowed = 1;
    cfg.attrs    = attrs;
    cfg.numAttrs = 1;
    cudaLaunchKernelEx(&cfg, mn_norm_kernel, X, mask, W, bias, out);
}